// round 3
// baseline (speedup 1.0000x reference)
#include <cuda_runtime.h>
#include <cuda_bf16.h>
#include <cstdint>

// ShiftLocalAttention2d: B=4, C=256 (8 heads x 32), H=W=48, 7x7 window, dil 1.
// CTA = (b, head) x 12-row band; 288 threads, each owns two vertically
// adjacent queries (union window 8x7 -> each smem K/V value read once, used
// by both queries). K/V halo in smem as float2-packed d-pairs: [d/2][row][x],
// conflict-free LDS.64. All P/V math via packed fma.rn.f32x2 (FFMA2) --
// halves fma-pipe and MIO issue pressure, bit-identical fp32 results.
// Softmax without running max (scores O(1), fp32 exp safe; shift-invariant
// softmax matches reference; center neighbor always valid -> l > 0).

#define TH        12
#define HALO_ROWS (TH + 6)          // 18
#define W_        48
#define NPOS      (HALO_ROWS * W_)  // 864
#define D_        32
#define D2        (D_ / 2)          // 16 float2 per position
#define SMEM_F2   (D2 * NPOS)       // 13824 float2 per tensor
#define SMEM_BYTES (2 * SMEM_F2 * 8)  // 221184
#define NTHREADS  288

union f2u {
    float2 f;
    unsigned long long u;
};

__device__ __forceinline__ void ffma2(unsigned long long& acc,
                                      unsigned long long a,
                                      unsigned long long b) {
    asm("fma.rn.f32x2 %0, %1, %2, %0;" : "+l"(acc) : "l"(a), "l"(b));
}

__global__ __launch_bounds__(NTHREADS, 1)
void natten7x7_kernel(const float* __restrict__ q,
                      const float* __restrict__ k,
                      const float* __restrict__ v,
                      float* __restrict__ out) {
    extern __shared__ float2 sm2[];
    float2* ks2 = sm2;              // [d2][row][x]
    float2* vs2 = sm2 + SMEM_F2;

    const int tid  = threadIdx.x;
    const int ty   = tid / W_;      // 0..5
    const int tx   = tid - ty * W_; // 0..47
    const int y0   = blockIdx.x * TH;
    const int head = blockIdx.y;
    const int b    = blockIdx.z;
    const int qy0  = y0 + 2 * ty;   // this thread's query rows: qy0, qy0+1

    const size_t base = ((size_t)(b * 8 + head)) * (D_ * 48 * 48);
    const float* kb = k + base;
    const float* vb = v + base;

    // ---- stage K/V halo into smem as d-paired float2 (zero OOB rows) ----
    for (int idx = tid; idx < NPOS; idx += NTHREADS) {
        const int row = idx / W_;
        const int x   = idx - row * W_;
        const int gy  = y0 - 3 + row;
        const bool ok = (unsigned)gy < 48u;
        const int g   = gy * 48 + x;
#pragma unroll
        for (int d2 = 0; d2 < D2; ++d2) {
            float2 kv = make_float2(0.f, 0.f);
            float2 vv = make_float2(0.f, 0.f);
            if (ok) {
                kv.x = kb[(2 * d2) * 2304 + g];
                kv.y = kb[(2 * d2 + 1) * 2304 + g];
                vv.x = vb[(2 * d2) * 2304 + g];
                vv.y = vb[(2 * d2 + 1) * 2304 + g];
            }
            ks2[d2 * NPOS + idx] = kv;
            vs2[d2 * NPOS + idx] = vv;
        }
    }

    // ---- load both queries as packed pairs (pre-scaled by 1/sqrt(32)) ----
    f2u q0r[D2], q1r[D2];
    {
        const float* qp = q + base + qy0 * 48 + tx;
#pragma unroll
        for (int d2 = 0; d2 < D2; ++d2) {
            q0r[d2].f.x = qp[(2 * d2) * 2304]          * 0.17677669529663689f;
            q0r[d2].f.y = qp[(2 * d2 + 1) * 2304]      * 0.17677669529663689f;
            q1r[d2].f.x = qp[(2 * d2) * 2304 + 48]     * 0.17677669529663689f;
            q1r[d2].f.y = qp[(2 * d2 + 1) * 2304 + 48] * 0.17677669529663689f;
        }
    }

    __syncthreads();

    // ---- attention over the pair's 8x7 union neighborhood ----
    float l0 = 0.f, l1 = 0.f;
    f2u o0[D2], o1[D2];
#pragma unroll
    for (int j = 0; j < D2; ++j) { o0[j].u = 0ull; o1[j].u = 0ull; }

#pragma unroll 1
    for (int r = 0; r < 8; ++r) {           // union rows: qy0-3 .. qy0+4
        const int  gy    = qy0 - 3 + r;
        const bool gok   = (unsigned)gy < 48u;
        const int  rbase = (2 * ty + r) * W_;
#pragma unroll
        for (int dx = 0; dx < 7; ++dx) {
            const int  col = tx + dx - 3;
            const bool ok  = gok && ((unsigned)col < 48u);
            const int  cc  = col < 0 ? 0 : (col > 47 ? 47 : col);

            // K dot: one LDS.64 per d-pair serves both queries (4 FMA chains)
            const float2* kp = ks2 + rbase + cc;
            f2u a0, a1, b0, b1;
            a0.u = a1.u = b0.u = b1.u = 0ull;
#pragma unroll
            for (int j = 0; j < D2; j += 2) {
                f2u k0; k0.f = kp[j * NPOS];
                f2u k1; k1.f = kp[(j + 1) * NPOS];
                ffma2(a0.u, q0r[j].u, k0.u);
                ffma2(b0.u, q1r[j].u, k0.u);
                ffma2(a1.u, q0r[j + 1].u, k1.u);
                ffma2(b1.u, q1r[j + 1].u, k1.u);
            }
            const float s0 = (a0.f.x + a0.f.y) + (a1.f.x + a1.f.y);
            const float s1 = (b0.f.x + b0.f.y) + (b1.f.x + b1.f.y);
            // q0 uses union rows 0..6, q1 uses 1..7
            const float p0 = (ok && r < 7) ? __expf(s0) : 0.f;
            const float p1 = (ok && r > 0) ? __expf(s1) : 0.f;
            l0 += p0;
            l1 += p1;

            f2u p0p, p1p;
            p0p.f = make_float2(p0, p0);
            p1p.f = make_float2(p1, p1);

            // V accum: one LDS.64 per d-pair serves both queries
            const float2* vp = vs2 + rbase + cc;
#pragma unroll
            for (int j = 0; j < D2; ++j) {
                f2u v2; v2.f = vp[j * NPOS];
                ffma2(o0[j].u, p0p.u, v2.u);
                ffma2(o1[j].u, p1p.u, v2.u);
            }
        }
    }

    // ---- normalize + store both query rows ----
    const float inv0 = 1.f / l0;
    const float inv1 = 1.f / l1;
    float* op = out + base + qy0 * 48 + tx;
#pragma unroll
    for (int j = 0; j < D2; ++j) {
        op[(2 * j) * 2304]          = o0[j].f.x * inv0;
        op[(2 * j + 1) * 2304]      = o0[j].f.y * inv0;
        op[(2 * j) * 2304 + 48]     = o1[j].f.x * inv1;
        op[(2 * j + 1) * 2304 + 48] = o1[j].f.y * inv1;
    }
}

extern "C" void kernel_launch(void* const* d_in, const int* in_sizes, int n_in,
                              void* d_out, int out_size) {
    const float* q = (const float*)d_in[0];
    const float* k = (const float*)d_in[1];
    const float* v = (const float*)d_in[2];
    float* out = (float*)d_out;

    cudaFuncSetAttribute(natten7x7_kernel,
                         cudaFuncAttributeMaxDynamicSharedMemorySize, SMEM_BYTES);

    dim3 grid(48 / TH, 8, 4);   // (4 row-bands, 8 heads, batch 4) = 128 CTAs
    natten7x7_kernel<<<grid, NTHREADS, SMEM_BYTES>>>(q, k, v, out);
}

// round 5
// speedup vs baseline: 1.1380x; 1.1380x over previous
#include <cuda_runtime.h>
#include <cuda_bf16.h>
#include <cstdint>

// ShiftLocalAttention2d: B=4, C=256 (8 heads x 32), H=W=48, 7x7 window, dil 1.
// CTA = (b, head) x 12-row band, 576 threads = 18 warps (2x round-3 occupancy).
// Lane pair (2*i, 2*i+1) owns two vertically adjacent queries (qy0, qy0+1);
// even lane computes d=[0,16), odd lane d=[16,32). Scores combined via one
// shfl.bfly per query; both lanes compute identical exp (fp32-exact).
// K/V halo in smem as float2 d-pairs, plane stride padded to 865 (odd) so the
// two d-half lane groups hit disjoint bank halves -> conflict-free LDS.64.
// Packed fma.rn.f32x2 throughout. Softmax without running max (scores O(1),
// fp32 exp safe, shift-invariant; center neighbor always valid -> l > 0).

#define TH        12
#define HALO_ROWS (TH + 6)            // 18
#define W_        48
#define NPOS      (HALO_ROWS * W_)    // 864 positions
#define PSTR      865                 // padded plane stride (float2), ODD
#define D_        32
#define DH2       8                   // float2 planes per d-half
#define SMEM_F2   (2 * DH2 * PSTR)    // 13840 float2 per tensor
#define SMEM_BYTES (2 * SMEM_F2 * 8)  // 221440
#define NTHREADS  576

union f2u {
    float2 f;
    unsigned long long u;
};

__device__ __forceinline__ void ffma2(unsigned long long& acc,
                                      unsigned long long a,
                                      unsigned long long b) {
    asm("fma.rn.f32x2 %0, %1, %2, %0;" : "+l"(acc) : "l"(a), "l"(b));
}

__global__ __launch_bounds__(NTHREADS, 1)
void natten7x7_kernel(const float* __restrict__ q,
                      const float* __restrict__ k,
                      const float* __restrict__ v,
                      float* __restrict__ out) {
    extern __shared__ float2 sm2[];
    float2* ks2 = sm2;                // [plane 0..15][pos], stride PSTR
    float2* vs2 = sm2 + SMEM_F2;

    const int tid = threadIdx.x;
    const int ty  = tid / 96;         // 0..5  (row-pair index)
    const int rem = tid - ty * 96;
    const int tx  = rem >> 1;         // 0..47
    const int ds  = rem & 1;          // d-half: 0 -> d[0,16), 1 -> d[16,32)
    const int y0   = blockIdx.x * TH;
    const int head = blockIdx.y;
    const int b    = blockIdx.z;
    const int qy0  = y0 + 2 * ty;

    const size_t base = ((size_t)(b * 8 + head)) * (D_ * 48 * 48);
    const float* kb = k + base;
    const float* vb = v + base;

    // ---- stage K/V halo into smem as d-paired float2 (zero OOB rows) ----
    for (int pos = tid; pos < NPOS; pos += NTHREADS) {
        const int row = pos / W_;
        const int x   = pos - row * W_;
        const int gy  = y0 - 3 + row;
        const bool ok = (unsigned)gy < 48u;
        const int g   = gy * 48 + x;
#pragma unroll
        for (int p = 0; p < 2 * DH2; ++p) {
            float2 kv = make_float2(0.f, 0.f);
            float2 vv = make_float2(0.f, 0.f);
            if (ok) {
                kv.x = kb[(2 * p) * 2304 + g];
                kv.y = kb[(2 * p + 1) * 2304 + g];
                vv.x = vb[(2 * p) * 2304 + g];
                vv.y = vb[(2 * p + 1) * 2304 + g];
            }
            ks2[p * PSTR + pos] = kv;
            vs2[p * PSTR + pos] = vv;
        }
    }

    // ---- load this lane's d-half of both queries (pre-scaled) ----
    f2u q0r[DH2], q1r[DH2];
    {
        const float* qp = q + base + qy0 * 48 + tx;
        const int db = ds * 16;       // scalar d offset of this half
#pragma unroll
        for (int j = 0; j < DH2; ++j) {
            const int d = db + 2 * j;
            q0r[j].f.x = qp[d * 2304]            * 0.17677669529663689f;
            q0r[j].f.y = qp[(d + 1) * 2304]      * 0.17677669529663689f;
            q1r[j].f.x = qp[d * 2304 + 48]       * 0.17677669529663689f;
            q1r[j].f.y = qp[(d + 1) * 2304 + 48] * 0.17677669529663689f;
        }
    }

    __syncthreads();

    // ---- attention over the pair's 8x7 union neighborhood ----
    float l0 = 0.f, l1 = 0.f;
    f2u o0[DH2], o1[DH2];
#pragma unroll
    for (int j = 0; j < DH2; ++j) { o0[j].u = 0ull; o1[j].u = 0ull; }

    const float2* kh = ks2 + (ds * DH2) * PSTR;   // this lane's K d-half
    const float2* vh = vs2 + (ds * DH2) * PSTR;

#pragma unroll 1
    for (int r = 0; r < 8; ++r) {                 // union rows qy0-3 .. qy0+4
        const int  gy  = qy0 - 3 + r;
        const bool gok = (unsigned)gy < 48u;
        const int  rb  = (2 * ty + r) * W_;
#pragma unroll
        for (int dx = 0; dx < 7; ++dx) {
            const int  col = tx + dx - 3;
            const bool ok  = gok && ((unsigned)col < 48u);
            const int  cc  = col < 0 ? 0 : (col > 47 ? 47 : col);

            // partial dots over this lane's 16 dims (one LDS.64 -> 2 queries)
            const float2* kp = kh + rb + cc;
            f2u a0, a1, b0, b1;
            a0.u = a1.u = b0.u = b1.u = 0ull;
#pragma unroll
            for (int j = 0; j < DH2; j += 2) {
                f2u k0; k0.f = kp[j * PSTR];
                f2u k1; k1.f = kp[(j + 1) * PSTR];
                ffma2(a0.u, q0r[j].u, k0.u);
                ffma2(b0.u, q1r[j].u, k0.u);
                ffma2(a1.u, q0r[j + 1].u, k1.u);
                ffma2(b1.u, q1r[j + 1].u, k1.u);
            }
            const float s0p = (a0.f.x + a0.f.y) + (a1.f.x + a1.f.y);
            const float s1p = (b0.f.x + b0.f.y) + (b1.f.x + b1.f.y);
            // combine d-halves across the lane pair (both lanes get full sum)
            const float s0 = s0p + __shfl_xor_sync(0xFFFFFFFFu, s0p, 1);
            const float s1 = s1p + __shfl_xor_sync(0xFFFFFFFFu, s1p, 1);
            // q0 uses union rows 0..6, q1 uses 1..7
            const float p0 = (ok && r < 7) ? __expf(s0) : 0.f;
            const float p1 = (ok && r > 0) ? __expf(s1) : 0.f;
            l0 += p0;
            l1 += p1;

            f2u p0p, p1p;
            p0p.f = make_float2(p0, p0);
            p1p.f = make_float2(p1, p1);

            // V accumulation over this lane's 16 dims
            const float2* vp = vh + rb + cc;
#pragma unroll
            for (int j = 0; j < DH2; ++j) {
                f2u v2; v2.f = vp[j * PSTR];
                ffma2(o0[j].u, p0p.u, v2.u);
                ffma2(o1[j].u, p1p.u, v2.u);
            }
        }
    }

    // ---- normalize + store this lane's d-half of both query rows ----
    const float inv0 = 1.f / l0;
    const float inv1 = 1.f / l1;
    float* op = out + base + qy0 * 48 + tx;
    const int db = ds * 16;
#pragma unroll
    for (int j = 0; j < DH2; ++j) {
        const int d = db + 2 * j;
        op[d * 2304]            = o0[j].f.x * inv0;
        op[(d + 1) * 2304]      = o0[j].f.y * inv0;
        op[d * 2304 + 48]       = o1[j].f.x * inv1;
        op[(d + 1) * 2304 + 48] = o1[j].f.y * inv1;
    }
}

extern "C" void kernel_launch(void* const* d_in, const int* in_sizes, int n_in,
                              void* d_out, int out_size) {
    const float* q = (const float*)d_in[0];
    const float* k = (const float*)d_in[1];
    const float* v = (const float*)d_in[2];
    float* out = (float*)d_out;

    cudaFuncSetAttribute(natten7x7_kernel,
                         cudaFuncAttributeMaxDynamicSharedMemorySize, SMEM_BYTES);

    dim3 grid(48 / TH, 8, 4);   // (4 row-bands, 8 heads, batch 4) = 128 CTAs
    natten7x7_kernel<<<grid, NTHREADS, SMEM_BYTES>>>(q, k, v, out);
}